// round 7
// baseline (speedup 1.0000x reference)
#include <cuda_runtime.h>
#include <math.h>

typedef unsigned int u32;

#define BT 32768
#define HD 4096
#define GN 16
#define EPG 16
#define EN 256
#define KCH 64              // fp32 per K chunk (256 B per row)
#define NCHUNK 64           // 4096 / 64
#define TPB 256
#define TOKT 64             // tokens per CTA tile
#define THR1 2.5e-3f        // group-gap flag threshold (phase1, 2-mma)
#define THR2 2e-4f          // expert-gap flag threshold (phase2, 3-mma)

#define AW 68               // padded row stride (words) -> conflict-free frags
#define A_WORDS (TOKT * AW)            // 4352
#define WP_WORDS (16 * AW)             // 1088 per plane
#define BUFW (A_WORDS + 2 * WP_WORDS)  // 6528 words = 26112 B
#define NSTG 4
#define SMEM_DYN (NSTG * BUFW * 4)     // 104448 B

__device__ __align__(16) float g_whi[272 * HD];  // rows 0-255 expert, 256-271 group
__device__ __align__(16) float g_wlo[272 * HD];
__device__ int g_cnt[GN];
__device__ int g_bucket[GN][BT];
__device__ int g_nfix;
__device__ int g_fix[BT];

// ---------------- primitives (sm_80-era, safe on generic compute_103) ----------
__device__ __forceinline__ void cpa16(u32 dst, const void* src) {
    asm volatile("cp.async.cg.shared.global [%0], [%1], 16;\n" :: "r"(dst), "l"(src));
}
#define CP_COMMIT() asm volatile("cp.async.commit_group;\n" ::: "memory")
#define CP_WAIT2()  asm volatile("cp.async.wait_group 2;\n" ::: "memory")

__device__ __forceinline__ void mma8(float* c, const u32* a, u32 b0, u32 b1) {
    asm volatile(
        "mma.sync.aligned.m16n8k8.row.col.f32.tf32.tf32.f32 "
        "{%0,%1,%2,%3}, {%4,%5,%6,%7}, {%8,%9}, {%0,%1,%2,%3};"
        : "+f"(c[0]), "+f"(c[1]), "+f"(c[2]), "+f"(c[3])
        : "r"(a[0]), "r"(a[1]), "r"(a[2]), "r"(a[3]), "r"(b0), "r"(b1));
}
__device__ __forceinline__ u32 tf32rn(float v) {
    u32 r; asm("cvt.rna.tf32.f32 %0, %1;" : "=r"(r) : "f"(v)); return r;
}
__device__ __forceinline__ u32 fb(float v) { return __float_as_uint(v); }

// ---------------- prep: W -> (hi = tf32rn(w), lo = w - hi) planes --------------
__global__ void prep_kernel(const float* __restrict__ gw, const float* __restrict__ ew) {
    u32 u = blockIdx.x * 256 + threadIdx.x;     // 278528 = 272 * 1024 quads
    if (u < GN) g_cnt[u] = 0;
    if (u == GN) g_nfix = 0;
    u32 row = u >> 10, q = (u & 1023) * 4;
    const float* src = (row < 256) ? ew + (size_t)row * HD + q
                                   : gw + (size_t)(row - 256) * HD + q;
    float4 v = *(const float4*)src;
    float4 h, l;
    h.x = __uint_as_float(tf32rn(v.x)); l.x = v.x - h.x;
    h.y = __uint_as_float(tf32rn(v.y)); l.y = v.y - h.y;
    h.z = __uint_as_float(tf32rn(v.z)); l.z = v.z - h.z;
    h.w = __uint_as_float(tf32rn(v.w)); l.w = v.w - h.w;
    *(float4*)&g_whi[(size_t)row * HD + q] = h;
    *(float4*)&g_wlo[(size_t)row * HD + q] = l;
}

// ---------------- MMA tile core -------------------------------------------------
// D[64 x 16] = A[64 x 4096] * W[16 x 4096]^T
// MODE 1: 2-mma (A raw, W hi+lo)  — phase 1 (argmax only)
// MODE 2: 3-mma split             — phase 2 (accurate logits)
struct P1Tok { int t0; __device__ int operator()(int r) const { return t0 + r; } };
struct P2Tok { const int* s; __device__ int operator()(int r) const { return s[r]; } };

template <int MODE, typename TOKF>
__device__ __forceinline__ void mma_tile(
    const float* __restrict__ hs, int wrow0, TOKF tokof,
    float* sb /* dynamic smem, NSTG*BUFW floats */, float* acc /* [4] */)
{
    const int tid = threadIdx.x;
    const int lane = tid & 31;
    const int wid = tid >> 5;
    const int lx = lane & 3, ly = lane >> 2;
    const int m0 = (wid >> 1) * 16;
    const int nb = (wid & 1) * 8;
    const u32 smb = (u32)__cvta_generic_to_shared(sb);

    const int arow = tid >> 2, aq = tid & 3;       // 64 rows x 64B quarters
    const int wplane = tid >> 7, wi = tid & 127;   // 2 planes x (16 rows x 8 units)
    const int wrow = wi >> 3, wu = wi & 7;
    const float* wsrc = (wplane ? g_wlo : g_whi) + (size_t)(wrow0 + wrow) * HD + wu * 8;

    acc[0] = acc[1] = acc[2] = acc[3] = 0.f;

    auto load = [&](int c) {
        const int st = c & (NSTG - 1);
        u32 base = smb + (u32)st * (BUFW * 4);
        int tok = tokof(arow);
        if (tok >= 0) {
            const char* sA = (const char*)(hs + (size_t)tok * HD + c * KCH) + aq * 64;
            u32 da = base + arow * (AW * 4) + aq * 64;
#pragma unroll
            for (int i = 0; i < 4; i++) cpa16(da + i * 16, sA + i * 16);
        }
        u32 dw = base + A_WORDS * 4 + wplane * (WP_WORDS * 4) + wrow * (AW * 4) + wu * 32;
        const char* sW = (const char*)(wsrc + (size_t)c * KCH);
        cpa16(dw, sW);
        cpa16(dw + 16, sW + 16);
    };

    load(0); CP_COMMIT();
    load(1); CP_COMMIT();
    load(2); CP_COMMIT();

    for (int c = 0; c < NCHUNK; c++) {
        CP_WAIT2();
        __syncthreads();
        const float* A = sb + (size_t)(c & (NSTG - 1)) * BUFW;
        const float* Wh = A + A_WORDS;
        const float* Wl = Wh + WP_WORDS;
#pragma unroll
        for (int kk = 0; kk < 8; kk++) {
            int ra = (m0 + ly) * AW + kk * 8 + lx;
            float a0 = A[ra], a1 = A[ra + 8 * AW], a2 = A[ra + 4], a3 = A[ra + 8 * AW + 4];
            int rb = (nb + ly) * AW + kk * 8 + lx;
            u32 bh0 = fb(Wh[rb]), bh1 = fb(Wh[rb + 4]);
            u32 bl0 = fb(Wl[rb]), bl1 = fb(Wl[rb + 4]);
            if (MODE == 1) {
                u32 a[4] = { fb(a0), fb(a1), fb(a2), fb(a3) };
                mma8(acc, a, bh0, bh1);
                mma8(acc, a, bl0, bl1);
            } else {
                u32 ahi[4] = { tf32rn(a0), tf32rn(a1), tf32rn(a2), tf32rn(a3) };
                u32 alo[4] = { fb(a0 - __uint_as_float(ahi[0])),
                               fb(a1 - __uint_as_float(ahi[1])),
                               fb(a2 - __uint_as_float(ahi[2])),
                               fb(a3 - __uint_as_float(ahi[3])) };
                mma8(acc, ahi, bh0, bh1);
                mma8(acc, alo, bh0, bh1);
                mma8(acc, ahi, bl0, bl1);
            }
        }
        if (c + 3 < NCHUNK) load(c + 3);
        CP_COMMIT();
    }
    __syncthreads();
}

// stage acc -> sC[64][18]
__device__ __forceinline__ void stage_c(float* sC, const float* acc) {
    const int tid = threadIdx.x;
    const int lane = tid & 31, wid = tid >> 5;
    const int lx = lane & 3, ly = lane >> 2;
    const int m0 = (wid >> 1) * 16, nb = (wid & 1) * 8;
    int row = m0 + ly, col = nb + 2 * lx;
    sC[row * 18 + col] = acc[0];       sC[row * 18 + col + 1] = acc[1];
    sC[(row + 8) * 18 + col] = acc[2]; sC[(row + 8) * 18 + col + 1] = acc[3];
}

// ---------------- phase 1: group logits, argmax, bucketing ---------------------
__global__ void __launch_bounds__(TPB) phase1_kernel(const float* __restrict__ hs)
{
    extern __shared__ float sb[];
    __shared__ int scnt[GN], sbase[GN], sbg[TOKT], sloff[TOKT];

    const int tid = threadIdx.x;
    const int token0 = blockIdx.x * TOKT;

    float acc[4];
    mma_tile<1>(hs, 256, P1Tok{token0}, sb, acc);

    float* sC = sb;
    stage_c(sC, acc);
    if (tid < GN) scnt[tid] = 0;
    __syncthreads();

    if (tid < TOKT) {
        const float* row = sC + tid * 18;
        float b1 = row[0], b2 = -1e30f; int bg = 0;
#pragma unroll
        for (int g = 1; g < GN; g++) {
            float v = row[g];
            if (v > b1) { b2 = b1; b1 = v; bg = g; }
            else if (v > b2) b2 = v;
        }
        sbg[tid] = bg;
        sloff[tid] = atomicAdd(&scnt[bg], 1);
        if (b1 - b2 < THR1) g_fix[atomicAdd(&g_nfix, 1)] = token0 + tid;
    }
    __syncthreads();
    if (tid < GN) sbase[tid] = atomicAdd(&g_cnt[tid], scnt[tid]);
    __syncthreads();
    if (tid < TOKT) g_bucket[sbg[tid]][sbase[sbg[tid]] + sloff[tid]] = token0 + tid;
}

// ---------------- phase 2: per-group expert GEMM + epilogue --------------------
__global__ void __launch_bounds__(TPB) phase2_kernel(
    const float* __restrict__ hs, float* __restrict__ out)
{
    extern __shared__ float sb[];
    __shared__ int stok[TOKT];

    const int tid = threadIdx.x;
    const int g = blockIdx.x;
    const int cnt = g_cnt[g];
    const size_t OSEL = (size_t)BT * EN, OWGT = OSEL + BT;

    for (int tile = blockIdx.y; tile * TOKT < cnt; tile += gridDim.y) {
        __syncthreads();
        if (tid < TOKT) {
            int i = tile * TOKT + tid;
            stok[tid] = (i < cnt) ? g_bucket[g][i] : -1;
        }
        __syncthreads();

        float acc[4];
        mma_tile<2>(hs, g * EPG, P2Tok{stok}, sb, acc);

        float* sC = sb;
        stage_c(sC, acc);
        __syncthreads();

        if (tid < TOKT && stok[tid] >= 0) {
            const float* row = sC + tid * 18;
            float m1 = row[0], m2 = -1e30f; int bi = 0;
#pragma unroll
            for (int e = 1; e < EPG; e++) {
                float v = row[e];
                if (v > m1) { m2 = m1; m1 = v; bi = e; }
                else if (v > m2) m2 = v;
            }
            float s = 0.f;
#pragma unroll
            for (int e = 0; e < EPG; e++) s += expf(row[e] - m1);
            int token = stok[tid];
            out[OSEL + token] = (float)(g * EPG + bi);
            out[OWGT + token] = 1.0f / s;
            if (m1 - m2 < THR2) g_fix[atomicAdd(&g_nfix, 1)] = token;
        }
        __syncthreads();

        // cooperative full [token, 256] row write (zeros outside block g)
        const int slot0 = tid >> 6, th = tid & 63;
#pragma unroll 4
        for (int p = 0; p < 16; p++) {
            int slot = p * 4 + slot0;
            int token = stok[slot];
            if (token >= 0) {
                float4 v = make_float4(0.f, 0.f, 0.f, 0.f);
                if ((th >> 2) == g) {
                    const float* row = sC + slot * 18 + (th & 3) * 4;
                    v = make_float4(row[0], row[1], row[2], row[3]);
                }
                *(float4*)&out[(size_t)token * EN + th * 4] = v;
            }
        }
    }
}

// ---------------- exact fp32 fixup: 512 threads, 1 warp per row ----------------
__global__ void __launch_bounds__(512) fixup_kernel(
    const float* __restrict__ hs, const float* __restrict__ gw,
    const float* __restrict__ ew, float* __restrict__ out)
{
    __shared__ float sg[GN], se[EPG];
    __shared__ int sbg_s;
    const int tid = threadIdx.x;
    const int wid = tid >> 5, lane = tid & 31;
    const size_t OSEL = (size_t)BT * EN, OWGT = OSEL + BT;
    const int n = g_nfix;

    for (int i = blockIdx.x; i < n; i += gridDim.x) {
        const int token = g_fix[i];
        const float4* x = (const float4*)(hs + (size_t)token * HD);
        {
            const float4* w = (const float4*)(gw + (size_t)wid * HD);
            float s = 0.f;
#pragma unroll 8
            for (int j = lane; j < HD / 4; j += 32) {
                float4 a = x[j], b = w[j];
                s += a.x * b.x + a.y * b.y + a.z * b.z + a.w * b.w;
            }
#pragma unroll
            for (int o = 16; o; o >>= 1) s += __shfl_xor_sync(0xFFFFFFFF, s, o);
            if (lane == 0) sg[wid] = s;
        }
        __syncthreads();
        if (tid == 0) {
            float best = sg[0]; int bg = 0;
#pragma unroll
            for (int g = 1; g < GN; g++) if (sg[g] > best) { best = sg[g]; bg = g; }
            sbg_s = bg;
        }
        __syncthreads();
        const int bg = sbg_s;
        {
            const float4* w = (const float4*)(ew + (size_t)(bg * EPG + wid) * HD);
            float s = 0.f;
#pragma unroll 8
            for (int j = lane; j < HD / 4; j += 32) {
                float4 a = x[j], b = w[j];
                s += a.x * b.x + a.y * b.y + a.z * b.z + a.w * b.w;
            }
#pragma unroll
            for (int o = 16; o; o >>= 1) s += __shfl_xor_sync(0xFFFFFFFF, s, o);
            if (lane == 0) se[wid] = s;
        }
        __syncthreads();
        if (tid == 0) {
            float m = se[0]; int bi = 0;
#pragma unroll
            for (int e = 1; e < EPG; e++) if (se[e] > m) { m = se[e]; bi = e; }
            float s = 0.f;
#pragma unroll
            for (int e = 0; e < EPG; e++) s += expf(se[e] - m);
            out[OSEL + token] = (float)(bg * EPG + bi);
            out[OWGT + token] = 1.0f / s;
        }
        if (tid < 64) {
            float4 v = make_float4(0.f, 0.f, 0.f, 0.f);
            if ((tid >> 2) == bg) {
                int lo = (tid & 3) * 4;
                v = make_float4(se[lo], se[lo + 1], se[lo + 2], se[lo + 3]);
            }
            *(float4*)&out[(size_t)token * EN + tid * 4] = v;
        }
        __syncthreads();
    }
}

extern "C" void kernel_launch(void* const* d_in, const int* in_sizes, int n_in,
                              void* d_out, int out_size) {
    const float* hs = (const float*)d_in[0];   // [32768, 4096]
    const float* gw = (const float*)d_in[1];   // [16, 4096]
    const float* ew = (const float*)d_in[2];   // [16, 16, 4096]
    float* out = (float*)d_out;

    cudaFuncSetAttribute(phase1_kernel,
                         cudaFuncAttributeMaxDynamicSharedMemorySize, SMEM_DYN);
    cudaFuncSetAttribute(phase2_kernel,
                         cudaFuncAttributeMaxDynamicSharedMemorySize, SMEM_DYN);

    prep_kernel<<<1088, 256>>>(gw, ew);
    phase1_kernel<<<BT / TOKT, TPB, SMEM_DYN>>>(hs);
    phase2_kernel<<<dim3(GN, 32), TPB, SMEM_DYN>>>(hs, out);
    fixup_kernel<<<256, 512>>>(hs, gw, ew, out);
}

// round 8
// speedup vs baseline: 1.2983x; 1.2983x over previous
#include <cuda_runtime.h>
#include <math.h>

typedef unsigned int u32;

#define BT 32768
#define HD 4096
#define GN 16
#define EPG 16
#define EN 256
#define KCH 32              // fp32 per K chunk (128 B per row)
#define NCHUNK 128          // 4096 / 32
#define TPB 256
#define TOKT 64             // tokens per CTA tile
#define THR1 2.5e-3f        // group-gap flag threshold (phase1, 1-mma tf32)
#define THR2 2e-3f          // expert-gap flag threshold (phase2, 2-mma)

#define AW 36               // padded row stride (words) -> conflict-free frags
#define A_WORDS (TOKT * AW)            // 2304
#define WP_WORDS (16 * AW)             // 576 per plane
#define BUFW (A_WORDS + 2 * WP_WORDS)  // 3456 words = 13824 B
#define NSTG 4

__device__ __align__(16) float g_whi[272 * HD];  // rows 0-255 expert, 256-271 group
__device__ __align__(16) float g_wlo[272 * HD];
__device__ int g_cnt[GN];
__device__ int g_bucket[GN][BT];
__device__ int g_nfix;
__device__ int g_fix[BT];

// ---------------- primitives (sm_80-era, safe on generic compute_103) ----------
__device__ __forceinline__ void cpa16(u32 dst, const void* src) {
    asm volatile("cp.async.cg.shared.global [%0], [%1], 16;\n" :: "r"(dst), "l"(src));
}
#define CP_COMMIT() asm volatile("cp.async.commit_group;\n" ::: "memory")
#define CP_WAIT2()  asm volatile("cp.async.wait_group 2;\n" ::: "memory")

__device__ __forceinline__ void mma8(float* c, const u32* a, u32 b0, u32 b1) {
    asm volatile(
        "mma.sync.aligned.m16n8k8.row.col.f32.tf32.tf32.f32 "
        "{%0,%1,%2,%3}, {%4,%5,%6,%7}, {%8,%9}, {%0,%1,%2,%3};"
        : "+f"(c[0]), "+f"(c[1]), "+f"(c[2]), "+f"(c[3])
        : "r"(a[0]), "r"(a[1]), "r"(a[2]), "r"(a[3]), "r"(b0), "r"(b1));
}
__device__ __forceinline__ u32 tf32rn(float v) {
    u32 r; asm("cvt.rna.tf32.f32 %0, %1;" : "=r"(r) : "f"(v)); return r;
}
__device__ __forceinline__ u32 fb(float v) { return __float_as_uint(v); }

// ---------------- prep: W -> (hi = tf32rn(w), lo = w - hi) planes --------------
__global__ void prep_kernel(const float* __restrict__ gw, const float* __restrict__ ew) {
    u32 u = blockIdx.x * 256 + threadIdx.x;     // 278528 = 272 * 1024 quads
    if (u < GN) g_cnt[u] = 0;
    if (u == GN) g_nfix = 0;
    u32 row = u >> 10, q = (u & 1023) * 4;
    const float* src = (row < 256) ? ew + (size_t)row * HD + q
                                   : gw + (size_t)(row - 256) * HD + q;
    float4 v = *(const float4*)src;
    float4 h, l;
    h.x = __uint_as_float(tf32rn(v.x)); l.x = v.x - h.x;
    h.y = __uint_as_float(tf32rn(v.y)); l.y = v.y - h.y;
    h.z = __uint_as_float(tf32rn(v.z)); l.z = v.z - h.z;
    h.w = __uint_as_float(tf32rn(v.w)); l.w = v.w - h.w;
    *(float4*)&g_whi[(size_t)row * HD + q] = h;
    *(float4*)&g_wlo[(size_t)row * HD + q] = l;
}

// ---------------- MMA tile core -------------------------------------------------
// D[64 x 16] = A[64 x 4096] * W[16 x 4096]^T
// MODE 1: 1-mma plain tf32 (A raw, W hi)      — phase 1 (argmax only)
// MODE 2: 2-mma (A raw, W hi + W lo)          — phase 2 (logits, ~2.6e-4 abs)
// Pipeline: wait(c) -> sync -> ISSUE load(c+3) -> compute(c)  (loads fly over MMAs)
struct P1Tok { int t0; __device__ int operator()(int r) const { return t0 + r; } };
struct P2Tok { const int* s; __device__ int operator()(int r) const { return s[r]; } };

template <int MODE, typename TOKF>
__device__ __forceinline__ void mma_tile(
    const float* __restrict__ hs, int wrow0, TOKF tokof,
    float (&sbuf)[NSTG][BUFW], float* acc /* [4] */)
{
    const int tid = threadIdx.x;
    const int lane = tid & 31;
    const int wid = tid >> 5;
    const int lx = lane & 3, ly = lane >> 2;
    const int m0 = (wid >> 1) * 16;
    const int nb = (wid & 1) * 8;
    const u32 smb = (u32)__cvta_generic_to_shared(&sbuf[0][0]);

    const int arow = tid >> 2, aq = tid & 3;       // 64 rows x 32B quarters
    const int wplane = tid >> 7, wi = tid & 127;   // 2 planes x (16 rows x 8 units)
    const int wrow = wi >> 3, wu = wi & 7;
    const float* wsrc = (wplane ? g_wlo : g_whi) + (size_t)(wrow0 + wrow) * HD + wu * 4;

    acc[0] = acc[1] = acc[2] = acc[3] = 0.f;

    auto load = [&](int c) {
        const int st = c & (NSTG - 1);
        u32 base = smb + (u32)st * (BUFW * 4);
        int tok = tokof(arow);
        if (tok >= 0) {
            const char* sA = (const char*)(hs + (size_t)tok * HD + c * KCH) + aq * 32;
            u32 da = base + arow * (AW * 4) + aq * 32;
            cpa16(da, sA);
            cpa16(da + 16, sA + 16);
        }
        if (MODE == 2 || wplane == 0)
            cpa16(base + A_WORDS * 4 + wplane * (WP_WORDS * 4) + wrow * (AW * 4) + wu * 16,
                  (const char*)(wsrc + (size_t)c * KCH));
    };

    load(0); CP_COMMIT();
    load(1); CP_COMMIT();
    load(2); CP_COMMIT();

    for (int c = 0; c < NCHUNK; c++) {
        CP_WAIT2();
        __syncthreads();
        // issue next loads BEFORE compute so DRAM streams under the MMA burst;
        // stage (c+3)&3 == (c-1)&3 was fully consumed before this barrier.
        if (c + 3 < NCHUNK) load(c + 3);
        CP_COMMIT();

        const float* A = sbuf[c & (NSTG - 1)];
        const float* Wh = A + A_WORDS;
        const float* Wl = Wh + WP_WORDS;
#pragma unroll
        for (int kk = 0; kk < 4; kk++) {
            int ra = (m0 + ly) * AW + kk * 8 + lx;
            u32 a[4] = { fb(A[ra]), fb(A[ra + 8 * AW]), fb(A[ra + 4]), fb(A[ra + 8 * AW + 4]) };
            int rb = (nb + ly) * AW + kk * 8 + lx;
            u32 bh0 = fb(Wh[rb]), bh1 = fb(Wh[rb + 4]);
            mma8(acc, a, bh0, bh1);
            if (MODE == 2) {
                u32 bl0 = fb(Wl[rb]), bl1 = fb(Wl[rb + 4]);
                mma8(acc, a, bl0, bl1);
            }
        }
        __syncthreads();
    }
}

// stage acc -> sC[64][18]
__device__ __forceinline__ void stage_c(float* sC, const float* acc) {
    const int tid = threadIdx.x;
    const int lane = tid & 31, wid = tid >> 5;
    const int lx = lane & 3, ly = lane >> 2;
    const int m0 = (wid >> 1) * 16, nb = (wid & 1) * 8;
    int row = m0 + ly, col = nb + 2 * lx;
    sC[row * 18 + col] = acc[0];       sC[row * 18 + col + 1] = acc[1];
    sC[(row + 8) * 18 + col] = acc[2]; sC[(row + 8) * 18 + col + 1] = acc[3];
}

// ---------------- phase 1: group logits, argmax, bucketing ---------------------
__global__ void __launch_bounds__(TPB) phase1_kernel(const float* __restrict__ hs)
{
    __shared__ float sbuf[NSTG][BUFW];
    __shared__ int scnt[GN], sbase[GN], sbg[TOKT], sloff[TOKT];

    const int tid = threadIdx.x;
    const int token0 = blockIdx.x * TOKT;

    float acc[4];
    mma_tile<1>(hs, 256, P1Tok{token0}, sbuf, acc);

    float* sC = &sbuf[0][0];
    stage_c(sC, acc);
    if (tid < GN) scnt[tid] = 0;
    __syncthreads();

    if (tid < TOKT) {
        const float* row = sC + tid * 18;
        float b1 = row[0], b2 = -1e30f; int bg = 0;
#pragma unroll
        for (int g = 1; g < GN; g++) {
            float v = row[g];
            if (v > b1) { b2 = b1; b1 = v; bg = g; }
            else if (v > b2) b2 = v;
        }
        sbg[tid] = bg;
        sloff[tid] = atomicAdd(&scnt[bg], 1);
        if (b1 - b2 < THR1) g_fix[atomicAdd(&g_nfix, 1)] = token0 + tid;
    }
    __syncthreads();
    if (tid < GN) sbase[tid] = atomicAdd(&g_cnt[tid], scnt[tid]);
    __syncthreads();
    if (tid < TOKT) g_bucket[sbg[tid]][sbase[sbg[tid]] + sloff[tid]] = token0 + tid;
}

// ---------------- phase 2: per-group expert GEMM + epilogue --------------------
__global__ void __launch_bounds__(TPB) phase2_kernel(
    const float* __restrict__ hs, float* __restrict__ out)
{
    __shared__ float sbuf[NSTG][BUFW];
    __shared__ int stok[TOKT];

    const int tid = threadIdx.x;
    const int g = blockIdx.x;
    const int cnt = g_cnt[g];
    const size_t OSEL = (size_t)BT * EN, OWGT = OSEL + BT;

    for (int tile = blockIdx.y; tile * TOKT < cnt; tile += gridDim.y) {
        __syncthreads();
        if (tid < TOKT) {
            int i = tile * TOKT + tid;
            stok[tid] = (i < cnt) ? g_bucket[g][i] : -1;
        }
        __syncthreads();

        float acc[4];
        mma_tile<2>(hs, g * EPG, P2Tok{stok}, sbuf, acc);

        float* sC = &sbuf[0][0];
        stage_c(sC, acc);
        __syncthreads();

        if (tid < TOKT && stok[tid] >= 0) {
            const float* row = sC + tid * 18;
            float m1 = row[0], m2 = -1e30f; int bi = 0;
#pragma unroll
            for (int e = 1; e < EPG; e++) {
                float v = row[e];
                if (v > m1) { m2 = m1; m1 = v; bi = e; }
                else if (v > m2) m2 = v;
            }
            float s = 0.f;
#pragma unroll
            for (int e = 0; e < EPG; e++) s += expf(row[e] - m1);
            int token = stok[tid];
            out[OSEL + token] = (float)(g * EPG + bi);
            out[OWGT + token] = 1.0f / s;
            if (m1 - m2 < THR2) g_fix[atomicAdd(&g_nfix, 1)] = token;
        }
        __syncthreads();

        // cooperative full [token, 256] row write (zeros outside block g)
        const int slot0 = tid >> 6, th = tid & 63;
#pragma unroll 4
        for (int p = 0; p < 16; p++) {
            int slot = p * 4 + slot0;
            int token = stok[slot];
            if (token >= 0) {
                float4 v = make_float4(0.f, 0.f, 0.f, 0.f);
                if ((th >> 2) == g) {
                    const float* row = sC + slot * 18 + (th & 3) * 4;
                    v = make_float4(row[0], row[1], row[2], row[3]);
                }
                *(float4*)&out[(size_t)token * EN + th * 4] = v;
            }
        }
    }
}

// ---------------- exact fp32 fixup: 512 threads, 1 warp per row ----------------
__global__ void __launch_bounds__(512) fixup_kernel(
    const float* __restrict__ hs, const float* __restrict__ gw,
    const float* __restrict__ ew, float* __restrict__ out)
{
    __shared__ float sg[GN], se[EPG];
    __shared__ int sbg_s;
    const int tid = threadIdx.x;
    const int wid = tid >> 5, lane = tid & 31;
    const size_t OSEL = (size_t)BT * EN, OWGT = OSEL + BT;
    const int n = g_nfix;

    for (int i = blockIdx.x; i < n; i += gridDim.x) {
        const int token = g_fix[i];
        const float4* x = (const float4*)(hs + (size_t)token * HD);
        {
            const float4* w = (const float4*)(gw + (size_t)wid * HD);
            float s = 0.f;
#pragma unroll 8
            for (int j = lane; j < HD / 4; j += 32) {
                float4 a = x[j], b = w[j];
                s += a.x * b.x + a.y * b.y + a.z * b.z + a.w * b.w;
            }
#pragma unroll
            for (int o = 16; o; o >>= 1) s += __shfl_xor_sync(0xFFFFFFFF, s, o);
            if (lane == 0) sg[wid] = s;
        }
        __syncthreads();
        if (tid == 0) {
            float best = sg[0]; int bg = 0;
#pragma unroll
            for (int g = 1; g < GN; g++) if (sg[g] > best) { best = sg[g]; bg = g; }
            sbg_s = bg;
        }
        __syncthreads();
        const int bg = sbg_s;
        {
            const float4* w = (const float4*)(ew + (size_t)(bg * EPG + wid) * HD);
            float s = 0.f;
#pragma unroll 8
            for (int j = lane; j < HD / 4; j += 32) {
                float4 a = x[j], b = w[j];
                s += a.x * b.x + a.y * b.y + a.z * b.z + a.w * b.w;
            }
#pragma unroll
            for (int o = 16; o; o >>= 1) s += __shfl_xor_sync(0xFFFFFFFF, s, o);
            if (lane == 0) se[wid] = s;
        }
        __syncthreads();
        if (tid == 0) {
            float m = se[0]; int bi = 0;
#pragma unroll
            for (int e = 1; e < EPG; e++) if (se[e] > m) { m = se[e]; bi = e; }
            float s = 0.f;
#pragma unroll
            for (int e = 0; e < EPG; e++) s += expf(se[e] - m);
            out[OSEL + token] = (float)(bg * EPG + bi);
            out[OWGT + token] = 1.0f / s;
        }
        if (tid < 64) {
            float4 v = make_float4(0.f, 0.f, 0.f, 0.f);
            if ((tid >> 2) == bg) {
                int lo = (tid & 3) * 4;
                v = make_float4(se[lo], se[lo + 1], se[lo + 2], se[lo + 3]);
            }
            *(float4*)&out[(size_t)token * EN + tid * 4] = v;
        }
        __syncthreads();
    }
}

extern "C" void kernel_launch(void* const* d_in, const int* in_sizes, int n_in,
                              void* d_out, int out_size) {
    const float* hs = (const float*)d_in[0];   // [32768, 4096]
    const float* gw = (const float*)d_in[1];   // [16, 4096]
    const float* ew = (const float*)d_in[2];   // [16, 16, 4096]
    float* out = (float*)d_out;

    prep_kernel<<<1088, 256>>>(gw, ew);
    phase1_kernel<<<BT / TOKT, TPB>>>(hs);
    phase2_kernel<<<dim3(GN, 32), TPB>>>(hs, out);
    fixup_kernel<<<256, 512>>>(hs, gw, ew, out);
}

// round 9
// speedup vs baseline: 1.4587x; 1.1236x over previous
#include <cuda_runtime.h>
#include <math.h>

typedef unsigned int u32;

#define BT 32768
#define HD 4096
#define GN 16
#define EPG 16
#define EN 256
#define KCH 32              // fp32 per K chunk (128 B per row)
#define NCHUNK 128          // 4096 / 32
#define TPB 256
#define TOKT 64             // tokens per CTA tile
#define P2Y 40              // phase2 y-grid: covers cnt up to 2560 in one tile/CTA
#define THR1 2.5e-3f        // group-gap flag threshold (phase1, 1-mma tf32)
#define THR2 2e-3f          // expert-gap flag threshold (phase2, 2-mma)

#define AW 36               // padded row stride (words) -> conflict-free frags
#define A_WORDS (TOKT * AW)            // 2304
#define WP_WORDS (16 * AW)             // 576 per plane
#define BUFW (A_WORDS + 2 * WP_WORDS)  // 3456 words = 13824 B
#define NSTG 4

__device__ __align__(16) float g_whi[272 * HD];  // rows 0-255 expert, 256-271 group
__device__ __align__(16) float g_wlo[272 * HD];
__device__ int g_cnt[GN];
__device__ int g_bucket[GN][BT];
__device__ int g_nfix;
__device__ int g_fix[BT];

// ---------------- primitives (sm_80-era, safe on generic compute_103) ----------
__device__ __forceinline__ void cpa16(u32 dst, const void* src) {
    asm volatile("cp.async.cg.shared.global [%0], [%1], 16;\n" :: "r"(dst), "l"(src));
}
#define CP_COMMIT() asm volatile("cp.async.commit_group;\n" ::: "memory")
#define CP_WAIT2()  asm volatile("cp.async.wait_group 2;\n" ::: "memory")

__device__ __forceinline__ void mma8(float* c, const u32* a, u32 b0, u32 b1) {
    asm volatile(
        "mma.sync.aligned.m16n8k8.row.col.f32.tf32.tf32.f32 "
        "{%0,%1,%2,%3}, {%4,%5,%6,%7}, {%8,%9}, {%0,%1,%2,%3};"
        : "+f"(c[0]), "+f"(c[1]), "+f"(c[2]), "+f"(c[3])
        : "r"(a[0]), "r"(a[1]), "r"(a[2]), "r"(a[3]), "r"(b0), "r"(b1));
}
__device__ __forceinline__ u32 tf32rn(float v) {
    u32 r; asm("cvt.rna.tf32.f32 %0, %1;" : "=r"(r) : "f"(v)); return r;
}
__device__ __forceinline__ u32 fb(float v) { return __float_as_uint(v); }

// ---------------- prep: W -> (hi = tf32rn(w), lo = w - hi) planes --------------
__global__ void prep_kernel(const float* __restrict__ gw, const float* __restrict__ ew) {
    u32 u = blockIdx.x * 256 + threadIdx.x;     // 278528 = 272 * 1024 quads
    if (u < GN) g_cnt[u] = 0;
    if (u == GN) g_nfix = 0;
    u32 row = u >> 10, q = (u & 1023) * 4;
    const float* src = (row < 256) ? ew + (size_t)row * HD + q
                                   : gw + (size_t)(row - 256) * HD + q;
    float4 v = *(const float4*)src;
    float4 h, l;
    h.x = __uint_as_float(tf32rn(v.x)); l.x = v.x - h.x;
    h.y = __uint_as_float(tf32rn(v.y)); l.y = v.y - h.y;
    h.z = __uint_as_float(tf32rn(v.z)); l.z = v.z - h.z;
    h.w = __uint_as_float(tf32rn(v.w)); l.w = v.w - h.w;
    *(float4*)&g_whi[(size_t)row * HD + q] = h;
    *(float4*)&g_wlo[(size_t)row * HD + q] = l;
}

// ---------------- MMA tile core -------------------------------------------------
// D[64 x 16] = A[64 x 4096] * W[16 x 4096]^T
// MODE 1: 1-mma plain tf32 (A raw, W hi)      — phase 1 (argmax only)
// MODE 2: 2-mma (A raw, W hi + W lo)          — phase 2 (logits, ~2.6e-4 abs)
// ONE barrier per chunk: wait(c) -> sync -> issue load(c+3) -> compute(c).
// The next iteration's top barrier separates compute(c) from the load that
// overwrites stage c&3, so no bottom barrier is needed.
struct P1Tok { int t0; __device__ int operator()(int r) const { return t0 + r; } };
struct P2Tok { const int* s; __device__ int operator()(int r) const { return s[r]; } };

template <int MODE, typename TOKF>
__device__ __forceinline__ void mma_tile(
    const float* __restrict__ hs, int wrow0, TOKF tokof,
    float (&sbuf)[NSTG][BUFW], float* acc /* [4] */)
{
    const int tid = threadIdx.x;
    const int lane = tid & 31;
    const int wid = tid >> 5;
    const int lx = lane & 3, ly = lane >> 2;
    const int m0 = (wid >> 1) * 16;
    const int nb = (wid & 1) * 8;
    const u32 smb = (u32)__cvta_generic_to_shared(&sbuf[0][0]);

    const int arow = tid >> 2, aq = tid & 3;       // 64 rows x 32B quarters
    const int wplane = tid >> 7, wi = tid & 127;   // 2 planes x (16 rows x 8 units)
    const int wrow = wi >> 3, wu = wi & 7;
    const float* wsrc = (wplane ? g_wlo : g_whi) + (size_t)(wrow0 + wrow) * HD + wu * 4;

    acc[0] = acc[1] = acc[2] = acc[3] = 0.f;

    auto load = [&](int c) {
        const int st = c & (NSTG - 1);
        u32 base = smb + (u32)st * (BUFW * 4);
        int tok = tokof(arow);
        if (tok >= 0) {
            const char* sA = (const char*)(hs + (size_t)tok * HD + c * KCH) + aq * 32;
            u32 da = base + arow * (AW * 4) + aq * 32;
            cpa16(da, sA);
            cpa16(da + 16, sA + 16);
        }
        if (MODE == 2 || wplane == 0)
            cpa16(base + A_WORDS * 4 + wplane * (WP_WORDS * 4) + wrow * (AW * 4) + wu * 16,
                  (const char*)(wsrc + (size_t)c * KCH));
    };

    load(0); CP_COMMIT();
    load(1); CP_COMMIT();
    load(2); CP_COMMIT();

    for (int c = 0; c < NCHUNK; c++) {
        CP_WAIT2();
        __syncthreads();
        // issue next loads BEFORE compute so DRAM streams under the MMA burst
        if (c + 3 < NCHUNK) load(c + 3);
        CP_COMMIT();

        const float* A = sbuf[c & (NSTG - 1)];
        const float* Wh = A + A_WORDS;
        const float* Wl = Wh + WP_WORDS;
#pragma unroll
        for (int kk = 0; kk < 4; kk++) {
            int ra = (m0 + ly) * AW + kk * 8 + lx;
            u32 a[4] = { fb(A[ra]), fb(A[ra + 8 * AW]), fb(A[ra + 4]), fb(A[ra + 8 * AW + 4]) };
            int rb = (nb + ly) * AW + kk * 8 + lx;
            u32 bh0 = fb(Wh[rb]), bh1 = fb(Wh[rb + 4]);
            mma8(acc, a, bh0, bh1);
            if (MODE == 2) {
                u32 bl0 = fb(Wl[rb]), bl1 = fb(Wl[rb + 4]);
                mma8(acc, a, bl0, bl1);
            }
        }
    }
    __syncthreads();   // all compute done before caller overlays sbuf[0]
}

// stage acc -> sC[64][18]
__device__ __forceinline__ void stage_c(float* sC, const float* acc) {
    const int tid = threadIdx.x;
    const int lane = tid & 31, wid = tid >> 5;
    const int lx = lane & 3, ly = lane >> 2;
    const int m0 = (wid >> 1) * 16, nb = (wid & 1) * 8;
    int row = m0 + ly, col = nb + 2 * lx;
    sC[row * 18 + col] = acc[0];       sC[row * 18 + col + 1] = acc[1];
    sC[(row + 8) * 18 + col] = acc[2]; sC[(row + 8) * 18 + col + 1] = acc[3];
}

// ---------------- phase 1: group logits, argmax, bucketing ---------------------
__global__ void __launch_bounds__(TPB) phase1_kernel(const float* __restrict__ hs)
{
    __shared__ float sbuf[NSTG][BUFW];
    __shared__ int scnt[GN], sbase[GN], sbg[TOKT], sloff[TOKT];

    const int tid = threadIdx.x;
    const int token0 = blockIdx.x * TOKT;

    float acc[4];
    mma_tile<1>(hs, 256, P1Tok{token0}, sbuf, acc);

    float* sC = &sbuf[0][0];
    stage_c(sC, acc);
    if (tid < GN) scnt[tid] = 0;
    __syncthreads();

    if (tid < TOKT) {
        const float* row = sC + tid * 18;
        float b1 = row[0], b2 = -1e30f; int bg = 0;
#pragma unroll
        for (int g = 1; g < GN; g++) {
            float v = row[g];
            if (v > b1) { b2 = b1; b1 = v; bg = g; }
            else if (v > b2) b2 = v;
        }
        sbg[tid] = bg;
        sloff[tid] = atomicAdd(&scnt[bg], 1);
        if (b1 - b2 < THR1) g_fix[atomicAdd(&g_nfix, 1)] = token0 + tid;
    }
    __syncthreads();
    if (tid < GN) sbase[tid] = atomicAdd(&g_cnt[tid], scnt[tid]);
    __syncthreads();
    if (tid < TOKT) g_bucket[sbg[tid]][sbase[sbg[tid]] + sloff[tid]] = token0 + tid;
}

// ---------------- phase 2: per-group expert GEMM + epilogue --------------------
__global__ void __launch_bounds__(TPB) phase2_kernel(
    const float* __restrict__ hs, float* __restrict__ out)
{
    __shared__ float sbuf[NSTG][BUFW];
    __shared__ int stok[TOKT];

    const int tid = threadIdx.x;
    const int g = blockIdx.x;
    const int cnt = g_cnt[g];
    const size_t OSEL = (size_t)BT * EN, OWGT = OSEL + BT;

    // gridDim.y sized so nearly every CTA runs at most ONE tile (no stragglers);
    // the loop remains as a correctness guard for pathological group counts.
    for (int tile = blockIdx.y; tile * TOKT < cnt; tile += gridDim.y) {
        __syncthreads();
        if (tid < TOKT) {
            int i = tile * TOKT + tid;
            stok[tid] = (i < cnt) ? g_bucket[g][i] : -1;
        }
        __syncthreads();

        float acc[4];
        mma_tile<2>(hs, g * EPG, P2Tok{stok}, sbuf, acc);

        float* sC = &sbuf[0][0];
        stage_c(sC, acc);
        __syncthreads();

        if (tid < TOKT && stok[tid] >= 0) {
            const float* row = sC + tid * 18;
            float m1 = row[0], m2 = -1e30f; int bi = 0;
#pragma unroll
            for (int e = 1; e < EPG; e++) {
                float v = row[e];
                if (v > m1) { m2 = m1; m1 = v; bi = e; }
                else if (v > m2) m2 = v;
            }
            float s = 0.f;
#pragma unroll
            for (int e = 0; e < EPG; e++) s += expf(row[e] - m1);
            int token = stok[tid];
            out[OSEL + token] = (float)(g * EPG + bi);
            out[OWGT + token] = 1.0f / s;
            if (m1 - m2 < THR2) g_fix[atomicAdd(&g_nfix, 1)] = token;
        }
        __syncthreads();

        // cooperative full [token, 256] row write (zeros outside block g)
        const int slot0 = tid >> 6, th = tid & 63;
#pragma unroll 4
        for (int p = 0; p < 16; p++) {
            int slot = p * 4 + slot0;
            int token = stok[slot];
            if (token >= 0) {
                float4 v = make_float4(0.f, 0.f, 0.f, 0.f);
                if ((th >> 2) == g) {
                    const float* row = sC + slot * 18 + (th & 3) * 4;
                    v = make_float4(row[0], row[1], row[2], row[3]);
                }
                *(float4*)&out[(size_t)token * EN + th * 4] = v;
            }
        }
    }
}

// ---------------- exact fp32 fixup: 512 threads, 1 warp per row ----------------
__global__ void __launch_bounds__(512) fixup_kernel(
    const float* __restrict__ hs, const float* __restrict__ gw,
    const float* __restrict__ ew, float* __restrict__ out)
{
    __shared__ float sg[GN], se[EPG];
    __shared__ int sbg_s;
    const int tid = threadIdx.x;
    const int wid = tid >> 5, lane = tid & 31;
    const size_t OSEL = (size_t)BT * EN, OWGT = OSEL + BT;
    const int n = g_nfix;

    for (int i = blockIdx.x; i < n; i += gridDim.x) {
        const int token = g_fix[i];
        const float4* x = (const float4*)(hs + (size_t)token * HD);
        {
            const float4* w = (const float4*)(gw + (size_t)wid * HD);
            float s = 0.f;
#pragma unroll 8
            for (int j = lane; j < HD / 4; j += 32) {
                float4 a = x[j], b = w[j];
                s += a.x * b.x + a.y * b.y + a.z * b.z + a.w * b.w;
            }
#pragma unroll
            for (int o = 16; o; o >>= 1) s += __shfl_xor_sync(0xFFFFFFFF, s, o);
            if (lane == 0) sg[wid] = s;
        }
        __syncthreads();
        if (tid == 0) {
            float best = sg[0]; int bg = 0;
#pragma unroll
            for (int g = 1; g < GN; g++) if (sg[g] > best) { best = sg[g]; bg = g; }
            sbg_s = bg;
        }
        __syncthreads();
        const int bg = sbg_s;
        {
            const float4* w = (const float4*)(ew + (size_t)(bg * EPG + wid) * HD);
            float s = 0.f;
#pragma unroll 8
            for (int j = lane; j < HD / 4; j += 32) {
                float4 a = x[j], b = w[j];
                s += a.x * b.x + a.y * b.y + a.z * b.z + a.w * b.w;
            }
#pragma unroll
            for (int o = 16; o; o >>= 1) s += __shfl_xor_sync(0xFFFFFFFF, s, o);
            if (lane == 0) se[wid] = s;
        }
        __syncthreads();
        if (tid == 0) {
            float m = se[0]; int bi = 0;
#pragma unroll
            for (int e = 1; e < EPG; e++) if (se[e] > m) { m = se[e]; bi = e; }
            float s = 0.f;
#pragma unroll
            for (int e = 0; e < EPG; e++) s += expf(se[e] - m);
            out[OSEL + token] = (float)(bg * EPG + bi);
            out[OWGT + token] = 1.0f / s;
        }
        if (tid < 64) {
            float4 v = make_float4(0.f, 0.f, 0.f, 0.f);
            if ((tid >> 2) == bg) {
                int lo = (tid & 3) * 4;
                v = make_float4(se[lo], se[lo + 1], se[lo + 2], se[lo + 3]);
            }
            *(float4*)&out[(size_t)token * EN + tid * 4] = v;
        }
        __syncthreads();
    }
}

extern "C" void kernel_launch(void* const* d_in, const int* in_sizes, int n_in,
                              void* d_out, int out_size) {
    const float* hs = (const float*)d_in[0];   // [32768, 4096]
    const float* gw = (const float*)d_in[1];   // [16, 4096]
    const float* ew = (const float*)d_in[2];   // [16, 16, 4096]
    float* out = (float*)d_out;

    prep_kernel<<<1088, 256>>>(gw, ew);
    phase1_kernel<<<BT / TOKT, TPB>>>(hs);
    phase2_kernel<<<dim3(GN, P2Y), TPB>>>(hs, out);
    fixup_kernel<<<256, 512>>>(hs, gw, ew, out);
}

// round 10
// speedup vs baseline: 1.5410x; 1.0564x over previous
#include <cuda_runtime.h>
#include <math.h>

typedef unsigned int u32;
typedef unsigned long long u64;

#define BT 32768
#define HD 4096
#define GN 16
#define EPG 16
#define EN 256
#define KCH 64              // fp32 per K chunk (256 B per row)
#define NCHUNK 64           // 4096 / 64
#define TPB 288             // 8 consumer warps + 1 producer warp
#define TOKT 64
#define P2Y 37              // 16*37 = 592 CTAs = one full wave at occ 4
#define THR1 2.5e-3f
#define THR2 2e-3f

#define AW 68               // padded row stride (words): 272 B, 16B-aligned, conflict-free
#define A_WORDS (TOKT * AW)            // 4352
#define WPL (16 * AW)                  // 1088 words per W plane
#define BUFW (A_WORDS + 2 * WPL)       // 6528 words = 26112 B
#define NSTG 2
#define SBUF_BYTES (NSTG * BUFW * 4)   // 52224
#define SMEM_DYN (SBUF_BYTES + 1024)   // 53248

#define N2WORDS (GN * NCHUNK * 2 * WPL)   // 2228224
#define N1WORDS (NCHUNK * WPL)            // 69632

__device__ __align__(16) float g_w2[(size_t)N2WORDS]; // [g][chunk][plane][row][68]
__device__ __align__(16) float g_w1[(size_t)N1WORDS]; // [chunk][row][68], hi only
__device__ int g_cnt[GN];
__device__ int g_bucket[GN][BT];
__device__ int g_nfix;
__device__ int g_fix[BT];

// ---------------- primitives ----------------------------------------------------
__device__ __forceinline__ void mma8(float* c, const u32* a, u32 b0, u32 b1) {
    asm volatile(
        "mma.sync.aligned.m16n8k8.row.col.f32.tf32.tf32.f32 "
        "{%0,%1,%2,%3}, {%4,%5,%6,%7}, {%8,%9}, {%0,%1,%2,%3};"
        : "+f"(c[0]), "+f"(c[1]), "+f"(c[2]), "+f"(c[3])
        : "r"(a[0]), "r"(a[1]), "r"(a[2]), "r"(a[3]), "r"(b0), "r"(b1));
}
__device__ __forceinline__ u32 tf32rn(float v) {
    u32 r; asm("cvt.rna.tf32.f32 %0, %1;" : "=r"(r) : "f"(v)); return r;
}
__device__ __forceinline__ u32 fb(float v) { return __float_as_uint(v); }

__device__ __forceinline__ void mbar_init(u32 a, u32 n) {
    asm volatile("mbarrier.init.shared.b64 [%0], %1;" :: "r"(a), "r"(n) : "memory");
}
__device__ __forceinline__ void mbar_arrive(u32 a) {
    asm volatile("mbarrier.arrive.shared.b64 _, [%0];" :: "r"(a) : "memory");
}
__device__ __forceinline__ void mbar_expect(u32 a, u32 b) {
    asm volatile("mbarrier.arrive.expect_tx.shared.b64 _, [%0], %1;"
                 :: "r"(a), "r"(b) : "memory");
}
__device__ __forceinline__ void mbar_wait(u32 a, u32 ph) {
    asm volatile("{\n\t.reg .pred P;\n\tW_%=:\n\t"
        "mbarrier.try_wait.parity.shared::cta.b64 P, [%0], %1;\n\t"
        "@!P bra W_%=;\n\t}" :: "r"(a), "r"(ph) : "memory");
}
__device__ __forceinline__ void bulk_g2s(u32 dst, const void* src, u32 bytes, u32 mbar) {
    asm volatile("cp.async.bulk.shared::cta.global.mbarrier::complete_tx::bytes "
                 "[%0], [%1], %2, [%3];"
                 :: "r"(dst), "l"(src), "r"(bytes), "r"(mbar) : "memory");
}
#define FENCE_PA() asm volatile("fence.proxy.async.shared::cta;" ::: "memory")

// ---------------- prep: build chunk-major padded W images (hi/lo split) --------
__global__ void prep_kernel(const float* __restrict__ gw, const float* __restrict__ ew) {
    u32 u = blockIdx.x * 256 + threadIdx.x;   // 2297856 = 8976*256
    if (u < GN) g_cnt[u] = 0;
    if (u == GN) g_nfix = 0;
    if (u < N2WORDS) {
        u32 word = u % AW;
        u32 r = (u / AW) & 15;
        u32 plane = (u / WPL) & 1;
        u32 chunk = (u / (2 * WPL)) & 63;
        u32 g = u / (NCHUNK * 2 * WPL);
        float o = 0.f;
        if (word < KCH) {
            float w = ew[(size_t)(g * EPG + r) * HD + chunk * KCH + word];
            float h = __uint_as_float(tf32rn(w));
            o = plane ? (w - h) : h;
        }
        g_w2[u] = o;
    } else {
        u32 v = u - N2WORDS;
        u32 word = v % AW;
        u32 r = (v / AW) & 15;
        u32 chunk = v / WPL;
        float o = 0.f;
        if (word < KCH)
            o = __uint_as_float(tf32rn(gw[(size_t)r * HD + chunk * KCH + word]));
        g_w1[v] = o;
    }
}

// ---------------- warp-specialized MMA tile core --------------------------------
// Producer warp (wid 8): per chunk, 64 row-bulks (256 B) + 1 W-chunk bulk.
// Consumer warps (wid 0-7): mbarrier-paced MMA, no __syncthreads in mainloop.
struct P1Tok { int t0; __device__ int operator()(int r) const { return t0 + r; } };
struct P2Tok { const int* s; __device__ int operator()(int r) const { return s[r]; } };

template <int MODE, typename TOKF>
__device__ __forceinline__ void tile_mma(
    const float* __restrict__ hs, const float* __restrict__ wimg, TOKF tokof,
    float (*sbuf)[BUFW], u32 mb, u32 txbytes, float* acc, int* phf, int* phe)
{
    const int tid = threadIdx.x;
    const int lane = tid & 31, wid = tid >> 5;
    const u32 smb = (u32)__cvta_generic_to_shared(&sbuf[0][0]);
    const u32 fullb[2]  = { mb, mb + 8 };
    const u32 emptyb[2] = { mb + 16, mb + 24 };
    const int wchw = (MODE == 1) ? WPL : 2 * WPL;

    if (wid == 8) {
        FENCE_PA();   // order prior generic smem writes (epilogue/stok) vs bulks
        for (int c = 0; c < NCHUNK; c++) {
            const int s = c & 1;
            mbar_wait(emptyb[s], phe[s]); phe[s] ^= 1;
            if (lane == 0) mbar_expect(fullb[s], txbytes);
            __syncwarp();
            const u32 base = smb + (u32)s * (BUFW * 4);
            const int r0 = lane, r1 = lane + 32;
            const int t0 = tokof(r0), t1 = tokof(r1);
            if (t0 >= 0)
                bulk_g2s(base + r0 * (AW * 4), hs + (size_t)t0 * HD + c * KCH,
                         KCH * 4, fullb[s]);
            if (t1 >= 0)
                bulk_g2s(base + r1 * (AW * 4), hs + (size_t)t1 * HD + c * KCH,
                         KCH * 4, fullb[s]);
            if (lane == 0)
                bulk_g2s(base + A_WORDS * 4, wimg + (size_t)c * wchw,
                         wchw * 4, fullb[s]);
        }
    } else {
        const int lx = lane & 3, ly = lane >> 2;
        const int m0 = (wid >> 1) * 16, nb = (wid & 1) * 8;
        acc[0] = acc[1] = acc[2] = acc[3] = 0.f;
        for (int c = 0; c < NCHUNK; c++) {
            const int s = c & 1;
            mbar_wait(fullb[s], phf[s]); phf[s] ^= 1;
            const float* A = sbuf[s];
            const float* Wh = A + A_WORDS;
            const float* Wl = Wh + WPL;
#pragma unroll
            for (int kk = 0; kk < 8; kk++) {
                int ra = (m0 + ly) * AW + kk * 8 + lx;
                u32 a[4] = { fb(A[ra]), fb(A[ra + 8 * AW]),
                             fb(A[ra + 4]), fb(A[ra + 8 * AW + 4]) };
                int rb = (nb + ly) * AW + kk * 8 + lx;
                mma8(acc, a, fb(Wh[rb]), fb(Wh[rb + 4]));
                if (MODE == 2) mma8(acc, a, fb(Wl[rb]), fb(Wl[rb + 4]));
            }
            if (lane == 0) mbar_arrive(emptyb[s]);
        }
    }
    __syncthreads();
}

__device__ __forceinline__ void barriers_setup(u32 mb, int tid) {
    if (tid == 0) {
        mbar_init(mb, 1);      mbar_init(mb + 8, 1);     // full: 1 expect-arrive
        mbar_init(mb + 16, 8); mbar_init(mb + 24, 8);    // empty: 8 warp arrives
        // pre-arm both empty barriers (complete phase 0) so producer's first
        // parity-0 waits pass unambiguously
        for (int i = 0; i < 8; i++) { mbar_arrive(mb + 16); mbar_arrive(mb + 24); }
        FENCE_PA();
    }
}

// stage acc -> sC[64][18]
__device__ __forceinline__ void stage_c(float* sC, const float* acc) {
    const int tid = threadIdx.x;
    const int lane = tid & 31, wid = tid >> 5;
    if (wid >= 8) return;
    const int lx = lane & 3, ly = lane >> 2;
    const int m0 = (wid >> 1) * 16, nb = (wid & 1) * 8;
    int row = m0 + ly, col = nb + 2 * lx;
    sC[row * 18 + col] = acc[0];       sC[row * 18 + col + 1] = acc[1];
    sC[(row + 8) * 18 + col] = acc[2]; sC[(row + 8) * 18 + col + 1] = acc[3];
}

// ---------------- phase 1: group logits, argmax, bucketing ---------------------
__global__ void __launch_bounds__(TPB) phase1_kernel(const float* __restrict__ hs)
{
    extern __shared__ char smem[];
    float (*sbuf)[BUFW] = reinterpret_cast<float(*)[BUFW]>(smem);
    const u32 mb = (u32)__cvta_generic_to_shared(smem) + SBUF_BYTES;
    int* si = (int*)(smem + SBUF_BYTES + 64);
    int* scnt = si;            // 16
    int* sbase = si + 16;      // 16
    int* sbg = si + 32;        // 64
    int* sloff = si + 96;      // 64

    const int tid = threadIdx.x;
    const int token0 = blockIdx.x * TOKT;

    barriers_setup(mb, tid);
    __syncthreads();

    int phf[2] = {0, 0}, phe[2] = {0, 0};
    float acc[4];
    tile_mma<1>(hs, g_w1, P1Tok{token0}, sbuf, mb,
                TOKT * KCH * 4 + WPL * 4, acc, phf, phe);

    float* sC = &sbuf[0][0];
    stage_c(sC, acc);
    if (tid < GN) scnt[tid] = 0;
    __syncthreads();

    if (tid < TOKT) {
        const float* row = sC + tid * 18;
        float b1 = row[0], b2 = -1e30f; int bg = 0;
#pragma unroll
        for (int g = 1; g < GN; g++) {
            float v = row[g];
            if (v > b1) { b2 = b1; b1 = v; bg = g; }
            else if (v > b2) b2 = v;
        }
        sbg[tid] = bg;
        sloff[tid] = atomicAdd(&scnt[bg], 1);
        if (b1 - b2 < THR1) g_fix[atomicAdd(&g_nfix, 1)] = token0 + tid;
    }
    __syncthreads();
    if (tid < GN) sbase[tid] = atomicAdd(&g_cnt[tid], scnt[tid]);
    __syncthreads();
    if (tid < TOKT) g_bucket[sbg[tid]][sbase[sbg[tid]] + sloff[tid]] = token0 + tid;
}

// ---------------- phase 2: per-group expert GEMM + epilogue --------------------
__global__ void __launch_bounds__(TPB) phase2_kernel(
    const float* __restrict__ hs, float* __restrict__ out)
{
    extern __shared__ char smem[];
    float (*sbuf)[BUFW] = reinterpret_cast<float(*)[BUFW]>(smem);
    const u32 mb = (u32)__cvta_generic_to_shared(smem) + SBUF_BYTES;
    int* stok = (int*)(smem + SBUF_BYTES + 64);

    const int tid = threadIdx.x;
    const int g = blockIdx.x;
    const int cnt = g_cnt[g];
    const float* wimg = g_w2 + (size_t)g * (NCHUNK * 2 * WPL);
    const size_t OSEL = (size_t)BT * EN, OWGT = OSEL + BT;

    barriers_setup(mb, tid);
    __syncthreads();

    int phf[2] = {0, 0}, phe[2] = {0, 0};

    for (int tile = blockIdx.y; tile * TOKT < cnt; tile += gridDim.y) {
        __syncthreads();
        if (tid < TOKT) {
            int i = tile * TOKT + tid;
            stok[tid] = (i < cnt) ? g_bucket[g][i] : -1;
        }
        __syncthreads();
        const int nvalid = min(TOKT, cnt - tile * TOKT);

        float acc[4];
        tile_mma<2>(hs, wimg, P2Tok{stok}, sbuf, mb,
                    (u32)nvalid * KCH * 4 + 2 * WPL * 4, acc, phf, phe);

        float* sC = &sbuf[0][0];
        stage_c(sC, acc);
        __syncthreads();

        if (tid < TOKT && stok[tid] >= 0) {
            const float* row = sC + tid * 18;
            float m1 = row[0], m2 = -1e30f; int bi = 0;
#pragma unroll
            for (int e = 1; e < EPG; e++) {
                float v = row[e];
                if (v > m1) { m2 = m1; m1 = v; bi = e; }
                else if (v > m2) m2 = v;
            }
            float s = 0.f;
#pragma unroll
            for (int e = 0; e < EPG; e++) s += expf(row[e] - m1);
            int token = stok[tid];
            out[OSEL + token] = (float)(g * EPG + bi);
            out[OWGT + token] = 1.0f / s;
            if (m1 - m2 < THR2) g_fix[atomicAdd(&g_nfix, 1)] = token;
        }
        __syncthreads();

        if (tid < 256) {
            const int slot0 = tid >> 6, th = tid & 63;
#pragma unroll 4
            for (int p = 0; p < 16; p++) {
                int slot = p * 4 + slot0;
                int token = stok[slot];
                if (token >= 0) {
                    float4 v = make_float4(0.f, 0.f, 0.f, 0.f);
                    if ((th >> 2) == g) {
                        const float* row = sC + slot * 18 + (th & 3) * 4;
                        v = make_float4(row[0], row[1], row[2], row[3]);
                    }
                    *(float4*)&out[(size_t)token * EN + th * 4] = v;
                }
            }
        }
    }
}

// ---------------- exact fp32 fixup ----------------------------------------------
__global__ void __launch_bounds__(512) fixup_kernel(
    const float* __restrict__ hs, const float* __restrict__ gw,
    const float* __restrict__ ew, float* __restrict__ out)
{
    __shared__ float sg[GN], se[EPG];
    __shared__ int sbg_s;
    const int tid = threadIdx.x;
    const int wid = tid >> 5, lane = tid & 31;
    const size_t OSEL = (size_t)BT * EN, OWGT = OSEL + BT;
    const int n = g_nfix;

    for (int i = blockIdx.x; i < n; i += gridDim.x) {
        const int token = g_fix[i];
        const float4* x = (const float4*)(hs + (size_t)token * HD);
        {
            const float4* w = (const float4*)(gw + (size_t)wid * HD);
            float s = 0.f;
#pragma unroll 8
            for (int j = lane; j < HD / 4; j += 32) {
                float4 a = x[j], b = w[j];
                s += a.x * b.x + a.y * b.y + a.z * b.z + a.w * b.w;
            }
#pragma unroll
            for (int o = 16; o; o >>= 1) s += __shfl_xor_sync(0xFFFFFFFF, s, o);
            if (lane == 0) sg[wid] = s;
        }
        __syncthreads();
        if (tid == 0) {
            float best = sg[0]; int bg = 0;
#pragma unroll
            for (int g = 1; g < GN; g++) if (sg[g] > best) { best = sg[g]; bg = g; }
            sbg_s = bg;
        }
        __syncthreads();
        const int bg = sbg_s;
        {
            const float4* w = (const float4*)(ew + (size_t)(bg * EPG + wid) * HD);
            float s = 0.f;
#pragma unroll 8
            for (int j = lane; j < HD / 4; j += 32) {
                float4 a = x[j], b = w[j];
                s += a.x * b.x + a.y * b.y + a.z * b.z + a.w * b.w;
            }
#pragma unroll
            for (int o = 16; o; o >>= 1) s += __shfl_xor_sync(0xFFFFFFFF, s, o);
            if (lane == 0) se[wid] = s;
        }
        __syncthreads();
        if (tid == 0) {
            float m = se[0]; int bi = 0;
#pragma unroll
            for (int e = 1; e < EPG; e++) if (se[e] > m) { m = se[e]; bi = e; }
            float s = 0.f;
#pragma unroll
            for (int e = 0; e < EPG; e++) s += expf(se[e] - m);
            out[OSEL + token] = (float)(bg * EPG + bi);
            out[OWGT + token] = 1.0f / s;
        }
        if (tid < 64) {
            float4 v = make_float4(0.f, 0.f, 0.f, 0.f);
            if ((tid >> 2) == bg) {
                int lo = (tid & 3) * 4;
                v = make_float4(se[lo], se[lo + 1], se[lo + 2], se[lo + 3]);
            }
            *(float4*)&out[(size_t)token * EN + tid * 4] = v;
        }
        __syncthreads();
    }
}

extern "C" void kernel_launch(void* const* d_in, const int* in_sizes, int n_in,
                              void* d_out, int out_size) {
    const float* hs = (const float*)d_in[0];   // [32768, 4096]
    const float* gw = (const float*)d_in[1];   // [16, 4096]
    const float* ew = (const float*)d_in[2];   // [16, 16, 4096]
    float* out = (float*)d_out;

    cudaFuncSetAttribute(phase1_kernel,
                         cudaFuncAttributeMaxDynamicSharedMemorySize, SMEM_DYN);
    cudaFuncSetAttribute(phase2_kernel,
                         cudaFuncAttributeMaxDynamicSharedMemorySize, SMEM_DYN);

    prep_kernel<<<8976, 256>>>(gw, ew);
    phase1_kernel<<<BT / TOKT, TPB, SMEM_DYN>>>(hs);
    phase2_kernel<<<dim3(GN, P2Y), TPB, SMEM_DYN>>>(hs, out);
    fixup_kernel<<<256, 512>>>(hs, gw, ew, out);
}

// round 11
// speedup vs baseline: 1.5545x; 1.0088x over previous
#include <cuda_runtime.h>
#include <math.h>

typedef unsigned int u32;
typedef unsigned long long u64;

#define BT 32768
#define HD 4096
#define GN 16
#define EPG 16
#define EN 256
#define KCH 64              // fp32 per K chunk (256 B per row)
#define NCHUNK 64           // 4096 / 64
#define TPB 288             // 8 consumer warps + 1 producer warp
#define TOKT 64
#define P2Y 37              // 16*37 = 592 CTAs = one full wave at occ 4
#define THR1 2.5e-3f
#define THR2 2e-3f

#define AW 68               // A row stride (words): 272 B, conflict-free frags
#define A_WORDS (TOKT * AW)            // 4352
#define WCH2 2560           // W chunk block words, 2 planes: [plane][nb][lane][20]
#define WCH1 1280           // 1 plane (phase 1)
#define BUFW (A_WORDS + WCH2)          // 6912 words = 27648 B
#define NSTG 2
#define SBUF_BYTES (NSTG * BUFW * 4)   // 55296
#define SMEM_DYN (SBUF_BYTES + 1024)   // 56320

#define N2WORDS (GN * NCHUNK * WCH2)   // 2,621,440
#define N1WORDS (NCHUNK * WCH1)        // 81,920

__device__ __align__(16) float g_w2[(size_t)N2WORDS]; // frag-major expert W hi/lo
__device__ __align__(16) float g_w1[(size_t)N1WORDS]; // frag-major group W hi
__device__ int g_cnt[GN];
__device__ int g_bucket[GN][BT];
__device__ int g_nfix;
__device__ int g_fix[BT];

// ---------------- primitives ----------------------------------------------------
__device__ __forceinline__ void mma8(float* c, const u32* a, u32 b0, u32 b1) {
    asm volatile(
        "mma.sync.aligned.m16n8k8.row.col.f32.tf32.tf32.f32 "
        "{%0,%1,%2,%3}, {%4,%5,%6,%7}, {%8,%9}, {%0,%1,%2,%3};"
        : "+f"(c[0]), "+f"(c[1]), "+f"(c[2]), "+f"(c[3])
        : "r"(a[0]), "r"(a[1]), "r"(a[2]), "r"(a[3]), "r"(b0), "r"(b1));
}
__device__ __forceinline__ u32 tf32rn(float v) {
    u32 r; asm("cvt.rna.tf32.f32 %0, %1;" : "=r"(r) : "f"(v)); return r;
}
__device__ __forceinline__ u32 fb(float v) { return __float_as_uint(v); }

__device__ __forceinline__ void mbar_init(u32 a, u32 n) {
    asm volatile("mbarrier.init.shared.b64 [%0], %1;" :: "r"(a), "r"(n) : "memory");
}
__device__ __forceinline__ void mbar_arrive(u32 a) {
    asm volatile("mbarrier.arrive.shared.b64 _, [%0];" :: "r"(a) : "memory");
}
__device__ __forceinline__ void mbar_expect(u32 a, u32 b) {
    asm volatile("mbarrier.arrive.expect_tx.shared.b64 _, [%0], %1;"
                 :: "r"(a), "r"(b) : "memory");
}
__device__ __forceinline__ void mbar_wait(u32 a, u32 ph) {
    asm volatile("{\n\t.reg .pred P;\n\tW_%=:\n\t"
        "mbarrier.try_wait.parity.shared::cta.b64 P, [%0], %1;\n\t"
        "@!P bra W_%=;\n\t}" :: "r"(a), "r"(ph) : "memory");
}
__device__ __forceinline__ void bulk_g2s(u32 dst, const void* src, u32 bytes, u32 mbar) {
    asm volatile("cp.async.bulk.shared::cta.global.mbarrier::complete_tx::bytes "
                 "[%0], [%1], %2, [%3];"
                 :: "r"(dst), "l"(src), "r"(bytes), "r"(mbar) : "memory");
}
#define FENCE_PA() asm volatile("fence.proxy.async.shared::cta;" ::: "memory")

// ---------------- prep: W -> fragment-major chunk blocks ------------------------
// g_w2 word layout: [g][chunk][plane][nbs][lane][20]; words 0..15 of each lane
// block hold frag pairs {W[nbs*8+ly][8kk+lx], W[..][8kk+lx+4]} for kk=0..7;
// words 16..19 pad (80 B lane stride -> conflict-free LDS.128).
__global__ void prep_kernel(const float* __restrict__ gw, const float* __restrict__ ew) {
    u32 q = blockIdx.x * 256 + threadIdx.x;     // one float4 per thread
    if (q < GN) g_cnt[q] = 0;
    if (q == GN) g_nfix = 0;
    const u32 NQ2 = N2WORDS / 4;
    if (q < NQ2) {
        u32 w = q * 4;
        u32 g = w / (NCHUNK * WCH2);
        u32 r = w - g * (NCHUNK * WCH2);
        u32 chunk = r / WCH2;  r -= chunk * WCH2;
        u32 plane = r / 1280;  r -= plane * 1280;
        u32 nbs = r / 640;     r -= nbs * 640;
        u32 lane = r / 20;
        u32 b = r - lane * 20;                   // 0,4,8,12,16
        float4 v = make_float4(0.f, 0.f, 0.f, 0.f);
        if (b < 16) {
            float* vp = (float*)&v;
            int row = g * EPG + nbs * 8 + (lane >> 2);
#pragma unroll
            for (int e = 0; e < 4; e++) {
                u32 widx = b + e, kk = widx >> 1, half = widx & 1;
                int col = chunk * KCH + kk * 8 + (lane & 3) + half * 4;
                float wv = ew[(size_t)row * HD + col];
                float h = __uint_as_float(tf32rn(wv));
                vp[e] = plane ? (wv - h) : h;
            }
        }
        *(float4*)&g_w2[w] = v;
    } else if (q < NQ2 + N1WORDS / 4) {
        u32 w = (q - NQ2) * 4;
        u32 chunk = w / WCH1;  u32 r = w - chunk * WCH1;
        u32 nbs = r / 640;     r -= nbs * 640;
        u32 lane = r / 20;
        u32 b = r - lane * 20;
        float4 v = make_float4(0.f, 0.f, 0.f, 0.f);
        if (b < 16) {
            float* vp = (float*)&v;
            int row = nbs * 8 + (lane >> 2);
#pragma unroll
            for (int e = 0; e < 4; e++) {
                u32 widx = b + e, kk = widx >> 1, half = widx & 1;
                int col = chunk * KCH + kk * 8 + (lane & 3) + half * 4;
                vp[e] = __uint_as_float(tf32rn(gw[(size_t)row * HD + col]));
            }
        }
        *(float4*)&g_w1[w] = v;
    }
}

// ---------------- warp-specialized MMA tile core --------------------------------
struct P1Tok { int t0; __device__ int operator()(int r) const { return t0 + r; } };
struct P2Tok { const int* s; __device__ int operator()(int r) const { return s[r]; } };

template <int MODE, typename TOKF>
__device__ __forceinline__ void tile_mma(
    const float* __restrict__ hs, const float* __restrict__ wimg, TOKF tokof,
    float (*sbuf)[BUFW], u32 mb, u32 txbytes, float* acc, int* phf, int* phe)
{
    const int tid = threadIdx.x;
    const int lane = tid & 31, wid = tid >> 5;
    const u32 smb = (u32)__cvta_generic_to_shared(&sbuf[0][0]);
    const u32 fullb[2]  = { mb, mb + 8 };
    const u32 emptyb[2] = { mb + 16, mb + 24 };
    const int wchw = (MODE == 1) ? WCH1 : WCH2;

    if (wid == 8) {
        FENCE_PA();
        for (int c = 0; c < NCHUNK; c++) {
            const int s = c & 1;
            mbar_wait(emptyb[s], phe[s]); phe[s] ^= 1;
            if (lane == 0) mbar_expect(fullb[s], txbytes);
            __syncwarp();
            const u32 base = smb + (u32)s * (BUFW * 4);
            const int r0 = lane, r1 = lane + 32;
            const int t0 = tokof(r0), t1 = tokof(r1);
            if (t0 >= 0)
                bulk_g2s(base + r0 * (AW * 4), hs + (size_t)t0 * HD + c * KCH,
                         KCH * 4, fullb[s]);
            if (t1 >= 0)
                bulk_g2s(base + r1 * (AW * 4), hs + (size_t)t1 * HD + c * KCH,
                         KCH * 4, fullb[s]);
            if (lane == 0)
                bulk_g2s(base + A_WORDS * 4, wimg + (size_t)c * wchw,
                         wchw * 4, fullb[s]);
        }
    } else {
        const int lx = lane & 3, ly = lane >> 2;
        const int m0 = (wid >> 1) * 16;
        acc[0] = acc[1] = acc[2] = acc[3] = 0.f;
        for (int c = 0; c < NCHUNK; c++) {
            const int s = c & 1;
            mbar_wait(fullb[s], phf[s]); phf[s] ^= 1;
            const float* A = sbuf[s];
            const float* whf = A + A_WORDS + (wid & 1) * 640 + lane * 20;
#pragma unroll
            for (int j = 0; j < 4; j++) {
                float4 H = *(const float4*)(whf + j * 4);
                float4 L;
                if (MODE == 2) L = *(const float4*)(whf + 1280 + j * 4);
#pragma unroll
                for (int p = 0; p < 2; p++) {
                    int kk = 2 * j + p;
                    int ra = (m0 + ly) * AW + kk * 8 + lx;
                    u32 a[4] = { fb(A[ra]), fb(A[ra + 8 * AW]),
                                 fb(A[ra + 4]), fb(A[ra + 8 * AW + 4]) };
                    mma8(acc, a, p ? fb(H.z) : fb(H.x), p ? fb(H.w) : fb(H.y));
                    if (MODE == 2)
                        mma8(acc, a, p ? fb(L.z) : fb(L.x), p ? fb(L.w) : fb(L.y));
                }
            }
            if (lane == 0) mbar_arrive(emptyb[s]);
        }
    }
    __syncthreads();
}

__device__ __forceinline__ void barriers_setup(u32 mb, int tid) {
    if (tid == 0) {
        mbar_init(mb, 1);      mbar_init(mb + 8, 1);     // full: expect-arrive
        mbar_init(mb + 16, 8); mbar_init(mb + 24, 8);    // empty: 8 warp arrives
        for (int i = 0; i < 8; i++) { mbar_arrive(mb + 16); mbar_arrive(mb + 24); }
        FENCE_PA();
    }
}

// stage acc -> sC[64][18]
__device__ __forceinline__ void stage_c(float* sC, const float* acc) {
    const int tid = threadIdx.x;
    const int lane = tid & 31, wid = tid >> 5;
    if (wid >= 8) return;
    const int lx = lane & 3, ly = lane >> 2;
    const int m0 = (wid >> 1) * 16, nb = (wid & 1) * 8;
    int row = m0 + ly, col = nb + 2 * lx;
    sC[row * 18 + col] = acc[0];       sC[row * 18 + col + 1] = acc[1];
    sC[(row + 8) * 18 + col] = acc[2]; sC[(row + 8) * 18 + col + 1] = acc[3];
}

// ---------------- phase 1: group logits, argmax, bucketing ---------------------
__global__ void __launch_bounds__(TPB) phase1_kernel(const float* __restrict__ hs)
{
    extern __shared__ char smem[];
    float (*sbuf)[BUFW] = reinterpret_cast<float(*)[BUFW]>(smem);
    const u32 mb = (u32)__cvta_generic_to_shared(smem) + SBUF_BYTES;
    int* si = (int*)(smem + SBUF_BYTES + 64);
    int* scnt = si;        // 16
    int* sbase = si + 16;  // 16
    int* sbg = si + 32;    // 64
    int* sloff = si + 96;  // 64

    const int tid = threadIdx.x;
    const int token0 = blockIdx.x * TOKT;

    barriers_setup(mb, tid);
    __syncthreads();

    int phf[2] = {0, 0}, phe[2] = {0, 0};
    float acc[4];
    tile_mma<1>(hs, g_w1, P1Tok{token0}, sbuf, mb,
                TOKT * KCH * 4 + WCH1 * 4, acc, phf, phe);

    float* sC = &sbuf[0][0];
    stage_c(sC, acc);
    if (tid < GN) scnt[tid] = 0;
    __syncthreads();

    if (tid < TOKT) {
        const float* row = sC + tid * 18;
        float b1 = row[0], b2 = -1e30f; int bg = 0;
#pragma unroll
        for (int g = 1; g < GN; g++) {
            float v = row[g];
            if (v > b1) { b2 = b1; b1 = v; bg = g; }
            else if (v > b2) b2 = v;
        }
        sbg[tid] = bg;
        sloff[tid] = atomicAdd(&scnt[bg], 1);
        if (b1 - b2 < THR1) g_fix[atomicAdd(&g_nfix, 1)] = token0 + tid;
    }
    __syncthreads();
    if (tid < GN) sbase[tid] = atomicAdd(&g_cnt[tid], scnt[tid]);
    __syncthreads();
    if (tid < TOKT) g_bucket[sbg[tid]][sbase[sbg[tid]] + sloff[tid]] = token0 + tid;
}

// ---------------- phase 2: per-group expert GEMM + epilogue --------------------
__global__ void __launch_bounds__(TPB) phase2_kernel(
    const float* __restrict__ hs, float* __restrict__ out)
{
    extern __shared__ char smem[];
    float (*sbuf)[BUFW] = reinterpret_cast<float(*)[BUFW]>(smem);
    const u32 mb = (u32)__cvta_generic_to_shared(smem) + SBUF_BYTES;
    int* stok = (int*)(smem + SBUF_BYTES + 64);

    const int tid = threadIdx.x;
    const int g = blockIdx.x;
    const int cnt = g_cnt[g];
    const float* wimg = g_w2 + (size_t)g * (NCHUNK * WCH2);
    const size_t OSEL = (size_t)BT * EN, OWGT = OSEL + BT;

    barriers_setup(mb, tid);
    __syncthreads();

    int phf[2] = {0, 0}, phe[2] = {0, 0};

    for (int tile = blockIdx.y; tile * TOKT < cnt; tile += gridDim.y) {
        __syncthreads();
        if (tid < TOKT) {
            int i = tile * TOKT + tid;
            stok[tid] = (i < cnt) ? g_bucket[g][i] : -1;
        }
        __syncthreads();
        const int nvalid = min(TOKT, cnt - tile * TOKT);

        float acc[4];
        tile_mma<2>(hs, wimg, P2Tok{stok}, sbuf, mb,
                    (u32)nvalid * KCH * 4 + WCH2 * 4, acc, phf, phe);

        float* sC = &sbuf[0][0];
        stage_c(sC, acc);
        __syncthreads();

        if (tid < TOKT && stok[tid] >= 0) {
            const float* row = sC + tid * 18;
            float m1 = row[0], m2 = -1e30f; int bi = 0;
#pragma unroll
            for (int e = 1; e < EPG; e++) {
                float v = row[e];
                if (v > m1) { m2 = m1; m1 = v; bi = e; }
                else if (v > m2) m2 = v;
            }
            float s = 0.f;
#pragma unroll
            for (int e = 0; e < EPG; e++) s += expf(row[e] - m1);
            int token = stok[tid];
            out[OSEL + token] = (float)(g * EPG + bi);
            out[OWGT + token] = 1.0f / s;
            if (m1 - m2 < THR2) g_fix[atomicAdd(&g_nfix, 1)] = token;
        }
        __syncthreads();

        if (tid < 256) {
            const int slot0 = tid >> 6, th = tid & 63;
#pragma unroll 4
            for (int p = 0; p < 16; p++) {
                int slot = p * 4 + slot0;
                int token = stok[slot];
                if (token >= 0) {
                    float4 v = make_float4(0.f, 0.f, 0.f, 0.f);
                    if ((th >> 2) == g) {
                        const float* row = sC + slot * 18 + (th & 3) * 4;
                        v = make_float4(row[0], row[1], row[2], row[3]);
                    }
                    *(float4*)&out[(size_t)token * EN + th * 4] = v;
                }
            }
        }
    }
}

// ---------------- exact fp32 fixup ----------------------------------------------
__global__ void __launch_bounds__(512) fixup_kernel(
    const float* __restrict__ hs, const float* __restrict__ gw,
    const float* __restrict__ ew, float* __restrict__ out)
{
    __shared__ float sg[GN], se[EPG];
    __shared__ int sbg_s;
    const int tid = threadIdx.x;
    const int wid = tid >> 5, lane = tid & 31;
    const size_t OSEL = (size_t)BT * EN, OWGT = OSEL + BT;
    const int n = g_nfix;

    for (int i = blockIdx.x; i < n; i += gridDim.x) {
        const int token = g_fix[i];
        const float4* x = (const float4*)(hs + (size_t)token * HD);
        {
            const float4* w = (const float4*)(gw + (size_t)wid * HD);
            float s = 0.f;
#pragma unroll 8
            for (int j = lane; j < HD / 4; j += 32) {
                float4 a = x[j], b = w[j];
                s += a.x * b.x + a.y * b.y + a.z * b.z + a.w * b.w;
            }
#pragma unroll
            for (int o = 16; o; o >>= 1) s += __shfl_xor_sync(0xFFFFFFFF, s, o);
            if (lane == 0) sg[wid] = s;
        }
        __syncthreads();
        if (tid == 0) {
            float best = sg[0]; int bg = 0;
#pragma unroll
            for (int g = 1; g < GN; g++) if (sg[g] > best) { best = sg[g]; bg = g; }
            sbg_s = bg;
        }
        __syncthreads();
        const int bg = sbg_s;
        {
            const float4* w = (const float4*)(ew + (size_t)(bg * EPG + wid) * HD);
            float s = 0.f;
#pragma unroll 8
            for (int j = lane; j < HD / 4; j += 32) {
                float4 a = x[j], b = w[j];
                s += a.x * b.x + a.y * b.y + a.z * b.z + a.w * b.w;
            }
#pragma unroll
            for (int o = 16; o; o >>= 1) s += __shfl_xor_sync(0xFFFFFFFF, s, o);
            if (lane == 0) se[wid] = s;
        }
        __syncthreads();
        if (tid == 0) {
            float m = se[0]; int bi = 0;
#pragma unroll
            for (int e = 1; e < EPG; e++) if (se[e] > m) { m = se[e]; bi = e; }
            float s = 0.f;
#pragma unroll
            for (int e = 0; e < EPG; e++) s += expf(se[e] - m);
            out[OSEL + token] = (float)(bg * EPG + bi);
            out[OWGT + token] = 1.0f / s;
        }
        if (tid < 64) {
            float4 v = make_float4(0.f, 0.f, 0.f, 0.f);
            if ((tid >> 2) == bg) {
                int lo = (tid & 3) * 4;
                v = make_float4(se[lo], se[lo + 1], se[lo + 2], se[lo + 3]);
            }
            *(float4*)&out[(size_t)token * EN + tid * 4] = v;
        }
        __syncthreads();
    }
}

extern "C" void kernel_launch(void* const* d_in, const int* in_sizes, int n_in,
                              void* d_out, int out_size) {
    const float* hs = (const float*)d_in[0];   // [32768, 4096]
    const float* gw = (const float*)d_in[1];   // [16, 4096]
    const float* ew = (const float*)d_in[2];   // [16, 16, 4096]
    float* out = (float*)d_out;

    cudaFuncSetAttribute(phase1_kernel,
                         cudaFuncAttributeMaxDynamicSharedMemorySize, SMEM_DYN);
    cudaFuncSetAttribute(phase2_kernel,
                         cudaFuncAttributeMaxDynamicSharedMemorySize, SMEM_DYN);

    prep_kernel<<<2640, 256>>>(gw, ew);
    phase1_kernel<<<BT / TOKT, TPB, SMEM_DYN>>>(hs);
    phase2_kernel<<<dim3(GN, P2Y), TPB, SMEM_DYN>>>(hs, out);
    fixup_kernel<<<256, 512>>>(hs, gw, ew, out);
}